// round 1
// baseline (speedup 1.0000x reference)
#include <cuda_runtime.h>

// KanLinear: out[b,o] = silu(x) @ scale_base + einsum('big,oig,io->bo', bases, spline_w, scale_spline)
// Recast as single GEMM: F[8192, 9216] @ W[9216, 1024]
//   feature index f = j*1024 + i ; j=0: silu, j=1+g: RBF basis g
#define IN_F  1024
#define OUT_F 1024
#define NG    8
#define BATCH 8192
#define KDIM  (IN_F * (NG + 1))   // 9216

typedef unsigned long long u64;

// Device-global scratch (allocation-free contract)
__device__ float g_W[(size_t)KDIM * OUT_F];   // [K][N]  36 MB
__device__ float g_F[(size_t)BATCH * KDIM];   // [M][K] 302 MB

// ---------------------------------------------------------------------------
// Phase A: effective weight  W[f, o]
// ---------------------------------------------------------------------------
__global__ void build_w_kernel(const float* __restrict__ scale_base,
                               const float* __restrict__ spline_weight,
                               const float* __restrict__ scale_spline) {
    int idx = blockIdx.x * blockDim.x + threadIdx.x;
    if (idx >= IN_F * OUT_F) return;
    int i = idx >> 10;        // / OUT_F
    int o = idx & (OUT_F - 1);

    float sb = scale_base[idx];    // [I, O]
    float ss = scale_spline[idx];  // [I, O]

    // j = 0 row: base path weight
    g_W[(size_t)i * OUT_F + o] = sb;

    // spline_weight layout [O, I, G]: 8 consecutive floats per (o, i) -> one 32B sector
    const float4* swp = reinterpret_cast<const float4*>(spline_weight + ((size_t)o * IN_F + i) * NG);
    float4 w0 = swp[0];
    float4 w1 = swp[1];
    g_W[((size_t)(1 + 0) * IN_F + i) * OUT_F + o] = w0.x * ss;
    g_W[((size_t)(1 + 1) * IN_F + i) * OUT_F + o] = w0.y * ss;
    g_W[((size_t)(1 + 2) * IN_F + i) * OUT_F + o] = w0.z * ss;
    g_W[((size_t)(1 + 3) * IN_F + i) * OUT_F + o] = w0.w * ss;
    g_W[((size_t)(1 + 4) * IN_F + i) * OUT_F + o] = w1.x * ss;
    g_W[((size_t)(1 + 5) * IN_F + i) * OUT_F + o] = w1.y * ss;
    g_W[((size_t)(1 + 6) * IN_F + i) * OUT_F + o] = w1.z * ss;
    g_W[((size_t)(1 + 7) * IN_F + i) * OUT_F + o] = w1.w * ss;
}

// ---------------------------------------------------------------------------
// Phase B: feature matrix  F[b, f]
// ---------------------------------------------------------------------------
__global__ void build_f_kernel(const float* __restrict__ x,
                               const float* __restrict__ grid,
                               const float* __restrict__ sigma_p) {
    int idx = blockIdx.x * blockDim.x + threadIdx.x;
    if (idx >= BATCH * IN_F) return;
    int b = idx >> 10;        // / IN_F
    int i = idx & (IN_F - 1);

    float xv = x[idx];
    float inv_sigma = __fdividef(1.0f, *sigma_p);
    size_t base = (size_t)b * KDIM;

    // silu(x) = x * sigmoid(x)
    g_F[base + i] = __fdividef(xv, 1.0f + __expf(-xv));

    const float4* gp = reinterpret_cast<const float4*>(grid + (size_t)i * NG);
    float4 g0 = gp[0];
    float4 g1 = gp[1];
    float gv[NG] = {g0.x, g0.y, g0.z, g0.w, g1.x, g1.y, g1.z, g1.w};
#pragma unroll
    for (int g = 0; g < NG; g++) {
        float t = (xv - gv[g]) * inv_sigma;
        g_F[base + (size_t)(1 + g) * IN_F + i] = __expf(-t * t);  // stores coalesced across i
    }
}

// ---------------------------------------------------------------------------
// Phase C: SGEMM 128x128x16, 256 threads, 8x8 per-thread tile, f32x2 FMAs
// ---------------------------------------------------------------------------
#define BM 128
#define BN 128
#define BK 16
#define NKT (KDIM / BK)   // 576

__device__ __forceinline__ u64 pack_dup(float a) {
    u64 r;
    asm("mov.b64 %0, {%1, %1};" : "=l"(r) : "f"(a));
    return r;
}
__device__ __forceinline__ void fma2(u64& acc, u64 a, u64 b) {
    asm("fma.rn.f32x2 %0, %1, %2, %0;" : "+l"(acc) : "l"(a), "l"(b));
}
__device__ __forceinline__ void unpack2(u64 v, float& lo, float& hi) {
    asm("mov.b64 {%0, %1}, %2;" : "=f"(lo), "=f"(hi) : "l"(v));
}

__global__ __launch_bounds__(256, 2) void sgemm_kernel(float* __restrict__ C) {
    __shared__ __align__(16) float As[2][BK][BM + 4];  // transposed A tile, +4 pad
    __shared__ __align__(16) float Bs[2][BK][BN];

    const int tid  = threadIdx.x;
    const int trow = tid >> 4;          // 0..15 -> 8 output rows each
    const int tcol = tid & 15;          // 0..15 -> 8 output cols each
    const int brow = blockIdx.y * BM;
    const int bcol = blockIdx.x * BN;

    // Global load mapping
    const int arow = tid >> 2;          // 0..63 (A rows, two passes: arow, arow+64)
    const int acol = (tid & 3) << 2;    // 0,4,8,12 (k within tile)
    const int bkr  = tid >> 5;          // 0..7  (B k-rows, two passes: bkr, bkr+8)
    const int bcl  = (tid & 31) << 2;   // 0..124

    const float* Abase = g_F + (size_t)(brow + arow) * KDIM + acol;
    const float* Bbase = g_W + (size_t)bkr * OUT_F + bcol + bcl;

    // --- load tile 0 ---
    float4 at0 = *(const float4*)(Abase);
    float4 at1 = *(const float4*)(Abase + (size_t)64 * KDIM);
    float4 bt0 = *(const float4*)(Bbase);
    float4 bt1 = *(const float4*)(Bbase + 8 * OUT_F);

    As[0][acol + 0][arow] = at0.x;
    As[0][acol + 1][arow] = at0.y;
    As[0][acol + 2][arow] = at0.z;
    As[0][acol + 3][arow] = at0.w;
    As[0][acol + 0][arow + 64] = at1.x;
    As[0][acol + 1][arow + 64] = at1.y;
    As[0][acol + 2][arow + 64] = at1.z;
    As[0][acol + 3][arow + 64] = at1.w;
    *(float4*)&Bs[0][bkr][bcl]     = bt0;
    *(float4*)&Bs[0][bkr + 8][bcl] = bt1;
    __syncthreads();

    u64 acc[8][4];
#pragma unroll
    for (int m = 0; m < 8; m++)
#pragma unroll
        for (int p = 0; p < 4; p++) acc[m][p] = 0ull;

    int buf = 0;
    for (int kt = 0; kt < NKT; kt++) {
        // prefetch next tile into registers
        if (kt + 1 < NKT) {
            const float* An = Abase + (size_t)(kt + 1) * BK;
            at0 = *(const float4*)(An);
            at1 = *(const float4*)(An + (size_t)64 * KDIM);
            const float* Bn = Bbase + (size_t)(kt + 1) * BK * OUT_F;
            bt0 = *(const float4*)(Bn);
            bt1 = *(const float4*)(Bn + 8 * OUT_F);
        }

        // compute on current buffer
#pragma unroll
        for (int k = 0; k < BK; k++) {
            float4 a0 = *(const float4*)&As[buf][k][trow * 8];
            float4 a1 = *(const float4*)&As[buf][k][trow * 8 + 4];
            u64 b2[4];
            b2[0] = *(const u64*)&Bs[buf][k][tcol * 8 + 0];
            b2[1] = *(const u64*)&Bs[buf][k][tcol * 8 + 2];
            b2[2] = *(const u64*)&Bs[buf][k][tcol * 8 + 4];
            b2[3] = *(const u64*)&Bs[buf][k][tcol * 8 + 6];
            float av[8] = {a0.x, a0.y, a0.z, a0.w, a1.x, a1.y, a1.z, a1.w};
#pragma unroll
            for (int m = 0; m < 8; m++) {
                u64 am = pack_dup(av[m]);
#pragma unroll
                for (int p = 0; p < 4; p++) fma2(acc[m][p], am, b2[p]);
            }
        }

        // store prefetched tile into the other buffer
        if (kt + 1 < NKT) {
            buf ^= 1;
            As[buf][acol + 0][arow] = at0.x;
            As[buf][acol + 1][arow] = at0.y;
            As[buf][acol + 2][arow] = at0.z;
            As[buf][acol + 3][arow] = at0.w;
            As[buf][acol + 0][arow + 64] = at1.x;
            As[buf][acol + 1][arow + 64] = at1.y;
            As[buf][acol + 2][arow + 64] = at1.z;
            As[buf][acol + 3][arow + 64] = at1.w;
            *(float4*)&Bs[buf][bkr][bcl]     = bt0;
            *(float4*)&Bs[buf][bkr + 8][bcl] = bt1;
            __syncthreads();
        }
    }

    // epilogue
    float* Cp = C + (size_t)(brow + trow * 8) * OUT_F + bcol + tcol * 8;
#pragma unroll
    for (int m = 0; m < 8; m++) {
        float o0, o1, o2, o3, o4, o5, o6, o7;
        unpack2(acc[m][0], o0, o1);
        unpack2(acc[m][1], o2, o3);
        unpack2(acc[m][2], o4, o5);
        unpack2(acc[m][3], o6, o7);
        *(float4*)(Cp + (size_t)m * OUT_F)     = make_float4(o0, o1, o2, o3);
        *(float4*)(Cp + (size_t)m * OUT_F + 4) = make_float4(o4, o5, o6, o7);
    }
}

// ---------------------------------------------------------------------------
extern "C" void kernel_launch(void* const* d_in, const int* in_sizes, int n_in,
                              void* d_out, int out_size) {
    const float* x             = (const float*)d_in[0];
    const float* scale_base    = (const float*)d_in[1];
    const float* spline_weight = (const float*)d_in[2];
    const float* scale_spline  = (const float*)d_in[3];
    const float* grid          = (const float*)d_in[4];
    const float* sigma         = (const float*)d_in[5];
    float* out = (float*)d_out;

    build_w_kernel<<<(IN_F * OUT_F + 255) / 256, 256>>>(scale_base, spline_weight, scale_spline);
    build_f_kernel<<<(BATCH * IN_F + 255) / 256, 256>>>(x, grid, sigma);
    sgemm_kernel<<<dim3(OUT_F / BN, BATCH / BM), 256>>>(out);
}

// round 4
// speedup vs baseline: 6.6001x; 6.6001x over previous
#include <cuda_runtime.h>
#include <cuda_fp16.h>

#define IN_F  1024
#define OUT_F 1024
#define NG    8
#define BATCH 8192
#define KDIM  9216

typedef unsigned int u32;
typedef unsigned long long u64;

// Device-global scratch (allocation-free contract)
__device__ __half g_Wh[(size_t)OUT_F * KDIM];   // [O][K] 18 MB, K-major
__device__ __half g_Fh[(size_t)BATCH * KDIM];   // [B][K] 151 MB, K-major

// ============================================================================
// PTX helpers
// ============================================================================
__device__ __forceinline__ u32 smem_u32(const void* p) {
    u32 a;
    asm("{ .reg .u64 t; cvta.to.shared.u64 t, %1; cvt.u32.u64 %0, t; }" : "=r"(a) : "l"(p));
    return a;
}
#define CP_ASYNC16(sa, ga) \
    asm volatile("cp.async.cg.shared.global [%0], [%1], 16;" :: "r"(sa), "l"(ga))
#define CP_COMMIT() asm volatile("cp.async.commit_group;")
#define CP_WAIT2()  asm volatile("cp.async.wait_group 2;")

#define LDSM4(r, addr) \
    asm volatile("ldmatrix.sync.aligned.m8n8.x4.shared.b16 {%0,%1,%2,%3}, [%4];" \
                 : "=r"((r)[0]), "=r"((r)[1]), "=r"((r)[2]), "=r"((r)[3]) : "r"(addr))

#define MMA16816(d, a, b) \
    asm volatile("mma.sync.aligned.m16n8k16.row.col.f32.f16.f16.f32 " \
                 "{%0,%1,%2,%3}, {%4,%5,%6,%7}, {%8,%9}, {%0,%1,%2,%3};" \
                 : "+f"((d)[0]), "+f"((d)[1]), "+f"((d)[2]), "+f"((d)[3]) \
                 : "r"((a)[0]), "r"((a)[1]), "r"((a)[2]), "r"((a)[3]), \
                   "r"((b)[0]), "r"((b)[1]))

// ============================================================================
// Phase A: effective weight W[o][k] in fp16  (k = j*1024 + i)
// ============================================================================
__global__ void build_w_kernel(const float* __restrict__ scale_base,
                               const float* __restrict__ spline_weight,
                               const float* __restrict__ scale_spline) {
    int idx = blockIdx.x * blockDim.x + threadIdx.x;
    if (idx >= IN_F * OUT_F) return;
    int o = idx >> 10;        // warp-constant
    int i = idx & 1023;       // consecutive in warp -> coalesced

    float sb = scale_base[(size_t)i * OUT_F + o];
    float ss = scale_spline[(size_t)i * OUT_F + o];
    __half* w = g_Wh + (size_t)o * KDIM;
    w[i] = __float2half_rn(sb);

    const float4* swp = reinterpret_cast<const float4*>(spline_weight + ((size_t)o * IN_F + i) * NG);
    float4 w0 = swp[0];
    float4 w1 = swp[1];
    w[1 * 1024 + i] = __float2half_rn(w0.x * ss);
    w[2 * 1024 + i] = __float2half_rn(w0.y * ss);
    w[3 * 1024 + i] = __float2half_rn(w0.z * ss);
    w[4 * 1024 + i] = __float2half_rn(w0.w * ss);
    w[5 * 1024 + i] = __float2half_rn(w1.x * ss);
    w[6 * 1024 + i] = __float2half_rn(w1.y * ss);
    w[7 * 1024 + i] = __float2half_rn(w1.z * ss);
    w[8 * 1024 + i] = __float2half_rn(w1.w * ss);
}

// ============================================================================
// Phase B: feature matrix F[b][k] in fp16
// ============================================================================
__global__ void build_f_kernel(const float* __restrict__ x,
                               const float* __restrict__ grid,
                               const float* __restrict__ sigma_p) {
    int idx = blockIdx.x * blockDim.x + threadIdx.x;
    if (idx >= BATCH * IN_F) return;
    int b = idx >> 10;
    int i = idx & (IN_F - 1);

    float xv = x[idx];
    float inv_sigma = __fdividef(1.0f, *sigma_p);
    size_t base = (size_t)b * KDIM;

    g_Fh[base + i] = __float2half_rn(__fdividef(xv, 1.0f + __expf(-xv)));  // silu

    const float4* gp = reinterpret_cast<const float4*>(grid + (size_t)i * NG);
    float4 g0 = gp[0];
    float4 g1 = gp[1];
    float gv[NG] = {g0.x, g0.y, g0.z, g0.w, g1.x, g1.y, g1.z, g1.w};
#pragma unroll
    for (int g = 0; g < NG; g++) {
        float t = (xv - gv[g]) * inv_sigma;
        g_Fh[base + (size_t)(1 + g) * IN_F + i] = __float2half_rn(__expf(-t * t));
    }
}

// ============================================================================
// Phase C: fp16 mma.sync GEMM: C[8192,1024] = F[8192,9216] @ W^T
//   BM=128 BN=128 BK=64 (128B rows, xor-swizzled 16B chunks), 4-stage cp.async
//   256 threads = 8 warps (2 M x 4 N), warp tile 64x32, m16n8k16
// ============================================================================
#define BM 128
#define BN 128
#define BK 64
#define NKT (KDIM / BK)           // 144
#define NSTG 4
#define STG_A 16384               // BM*BK*2
#define STG_B 16384
#define STG_BYTES (STG_A + STG_B) // 32768
#define SMEM_TOTAL (NSTG * STG_BYTES)  // 131072

__device__ __forceinline__ void load_stage(u32 sbase, const __half* gA, const __half* gB,
                                           int kt, int lr, int lc, u32 phys) {
    const u32 sA = sbase + (u32)(kt & 3) * STG_BYTES;
    const u32 sB = sA + STG_A;
    const __half* ga = gA + (size_t)lr * KDIM + (size_t)kt * BK + lc * 8;
    const __half* gb = gB + (size_t)lr * KDIM + (size_t)kt * BK + lc * 8;
#pragma unroll
    for (int it = 0; it < 4; it++) {
        u32 off = (u32)(lr + 32 * it) * 128 + phys;
        CP_ASYNC16(sA + off, ga + (size_t)(32 * it) * KDIM);
        CP_ASYNC16(sB + off, gb + (size_t)(32 * it) * KDIM);
    }
    CP_COMMIT();
}

__global__ void __launch_bounds__(256, 1)
gemm_kernel(float* __restrict__ C) {
    extern __shared__ __align__(1024) char smem[];
    const u32 sbase = smem_u32(smem);
    const int tid = threadIdx.x;
    const int lane = tid & 31;
    const int wid = tid >> 5;
    const int wm = wid & 1;       // 2 warps along M
    const int wn = wid >> 1;      // 4 warps along N
    const int brow = blockIdx.y * BM;
    const int bcol = blockIdx.x * BN;

    const __half* gA = g_Fh + (size_t)brow * KDIM;
    const __half* gB = g_Wh + (size_t)bcol * KDIM;

    // cp.async mapping: thread -> (row lr, 16B chunk lc); xor swizzle on chunk
    const int lr = tid >> 3;            // 0..31
    const int lc = tid & 7;             // 0..7
    const u32 phys = (u32)((lc ^ (lr & 7)) << 4);

    float acc[4][4][4];
#pragma unroll
    for (int mi = 0; mi < 4; mi++)
#pragma unroll
        for (int ni = 0; ni < 4; ni++)
#pragma unroll
            for (int q = 0; q < 4; q++) acc[mi][ni][q] = 0.0f;

    // prologue: fill 3 stages
    load_stage(sbase, gA, gB, 0, lr, lc, phys);
    load_stage(sbase, gA, gB, 1, lr, lc, phys);
    load_stage(sbase, gA, gB, 2, lr, lc, phys);

    const int j = lane >> 3;            // ldmatrix sub-matrix id
    const int i8 = lane & 7;            // row within sub-matrix
    const int arow_in = (j & 1) * 8 + i8;
    const int nrow_in = (j >> 1) * 8 + i8;

    for (int kt = 0; kt < NKT; kt++) {
        CP_WAIT2();
        __syncthreads();
        const u32 sA = sbase + (u32)(kt & 3) * STG_BYTES;
        const u32 sB = sA + STG_A;

#pragma unroll
        for (int ks = 0; ks < 4; ks++) {
            u32 a[4][4];
            u32 b[4][2];
            const int cA = ks * 2 + (j >> 1);       // A: matrices 2,3 take k8-15
            const int cB = ks * 2 + (j & 1);        // B: matrices 1,3 take k8-15
#pragma unroll
            for (int mi = 0; mi < 4; mi++) {
                int ar = wm * 64 + mi * 16 + arow_in;
                u32 addr = sA + (u32)ar * 128 + (u32)((cA ^ i8) << 4);
                LDSM4(a[mi], addr);
            }
#pragma unroll
            for (int p = 0; p < 2; p++) {
                int br = wn * 32 + p * 16 + nrow_in;
                u32 addr = sB + (u32)br * 128 + (u32)((cB ^ i8) << 4);
                u32 r[4];
                LDSM4(r, addr);
                b[2 * p][0] = r[0]; b[2 * p][1] = r[1];
                b[2 * p + 1][0] = r[2]; b[2 * p + 1][1] = r[3];
            }
#pragma unroll
            for (int mi = 0; mi < 4; mi++)
#pragma unroll
                for (int ni = 0; ni < 4; ni++)
                    MMA16816(acc[mi][ni], a[mi], b[ni]);
        }
        __syncthreads();
        if (kt + 3 < NKT) load_stage(sbase, gA, gB, kt + 3, lr, lc, phys);
        else CP_COMMIT();   // keep group count advancing for CP_WAIT2 bookkeeping
    }

    // epilogue
    const int r0 = brow + wm * 64 + (lane >> 2);
    const int c0 = bcol + wn * 32 + 2 * (lane & 3);
#pragma unroll
    for (int mi = 0; mi < 4; mi++) {
#pragma unroll
        for (int ni = 0; ni < 4; ni++) {
            float* p = C + (size_t)(r0 + mi * 16) * OUT_F + c0 + ni * 8;
            *(float2*)p = make_float2(acc[mi][ni][0], acc[mi][ni][1]);
            *(float2*)(p + (size_t)8 * OUT_F) = make_float2(acc[mi][ni][2], acc[mi][ni][3]);
        }
    }
}

// ============================================================================
extern "C" void kernel_launch(void* const* d_in, const int* in_sizes, int n_in,
                              void* d_out, int out_size) {
    const float* x             = (const float*)d_in[0];
    const float* scale_base    = (const float*)d_in[1];
    const float* spline_weight = (const float*)d_in[2];
    const float* scale_spline  = (const float*)d_in[3];
    const float* grid          = (const float*)d_in[4];
    const float* sigma         = (const float*)d_in[5];
    float* out = (float*)d_out;

    static bool attr_set = false;
    if (!attr_set) {
        cudaFuncSetAttribute(gemm_kernel,
                             cudaFuncAttributeMaxDynamicSharedMemorySize, SMEM_TOTAL);
        attr_set = true;
    }

    build_w_kernel<<<(IN_F * OUT_F + 255) / 256, 256>>>(scale_base, spline_weight, scale_spline);
    build_f_kernel<<<(BATCH * IN_F + 255) / 256, 256>>>(x, grid, sigma);
    gemm_kernel<<<dim3(OUT_F / BN, BATCH / BM), 256, SMEM_TOTAL>>>(out);
}